// round 17
// baseline (speedup 1.0000x reference)
#include <cuda_runtime.h>
#include <cuda_fp16.h>
#include <math.h>

#define T_TOK 8192
#define HD    2048
#define NE    8
#define ID    1408
#define TWO_I 2816
#define NA    16384
#define NA_PAD 17408   // expert regions 128-aligned (R4 fix)
#define MAX_TILES 144
#define RT_TILES 136
#define NSTG 4
// gemm1 stage: A 6144 (48B rows) + Bg 2304 (144B rows) + Bu 2304 = 10752
#define STG1B 10752
#define SMEM_G1 (NSTG * STG1B)    // 43008
// gemm2 stage: A 6144 + B 4352 (272B rows) = 10496
#define STG2B 10496
#define SMEM_G2 (NSTG * STG2B)    // 41984

// ---------------- scratch ----------------
__device__ __half g_xin[(size_t)NA_PAD * HD];      // fp16(x*p), expert-grouped [m][k]
__device__ __half g_hidden[(size_t)NA_PAD * ID];   // fp16 routed swiglu [m][k]
__device__ __half g_shidden[(size_t)T_TOK * ID];   // fp16 shared swiglu [m][k]
__device__ __half g_xh[(size_t)T_TOK * HD];        // fp16(x) [m][k]
// fp16 weight mirrors in ORIGINAL [k][n] layout (no transpose)
__device__ __half g_wgu_h[(size_t)NE * HD * TWO_I];
__device__ __half g_wd_h[(size_t)NE * ID * HD];
__device__ __half g_wsgu_h[(size_t)HD * TWO_I];
__device__ __half g_wsd_h[(size_t)ID * HD];
__device__ int   g_top_e[NA];
__device__ float g_top_p[NA];
__device__ float g_gate[T_TOK];
__device__ int   g_cnt[NE], g_off[NE], g_fill[NE];
__device__ int   g_row_token[NA_PAD];
__device__ int   g_tile_e[MAX_TILES], g_tile_row0[MAX_TILES], g_tile_rows[MAX_TILES];
__device__ int   g_ntiles;

// ---------------- helpers ----------------
__device__ __forceinline__ void mma_f16(float* c, const unsigned* a, unsigned b0, unsigned b1) {
    asm volatile(
        "mma.sync.aligned.m16n8k16.row.col.f32.f16.f16.f32 "
        "{%0,%1,%2,%3}, {%4,%5,%6,%7}, {%8,%9}, {%0,%1,%2,%3};\n"
        : "+f"(c[0]), "+f"(c[1]), "+f"(c[2]), "+f"(c[3])
        : "r"(a[0]), "r"(a[1]), "r"(a[2]), "r"(a[3]), "r"(b0), "r"(b1));
}
__device__ __forceinline__ void ldsm4(unsigned* r, unsigned addr) {
    asm volatile("ldmatrix.sync.aligned.m8n8.x4.shared.b16 {%0,%1,%2,%3}, [%4];"
                 : "=r"(r[0]), "=r"(r[1]), "=r"(r[2]), "=r"(r[3]) : "r"(addr));
}
__device__ __forceinline__ void ldsm4t(unsigned* r, unsigned addr) {
    asm volatile("ldmatrix.sync.aligned.m8n8.x4.trans.shared.b16 {%0,%1,%2,%3}, [%4];"
                 : "=r"(r[0]), "=r"(r[1]), "=r"(r[2]), "=r"(r[3]) : "r"(addr));
}
__device__ __forceinline__ void cp16s(unsigned dst, const void* src) {
    asm volatile("cp.async.cg.shared.global [%0], [%1], 16;\n" :: "r"(dst), "l"(src));
}
__device__ __forceinline__ void cp_commit() { asm volatile("cp.async.commit_group;\n"); }
__device__ __forceinline__ void cp_wait2()  { asm volatile("cp.async.wait_group 2;\n"); }

// ---------------- small kernels ----------------
__global__ void router_kernel(const float* __restrict__ x,
                              const float* __restrict__ wr,
                              const float* __restrict__ wsg) {
    int gw   = (blockIdx.x * blockDim.x + threadIdx.x) >> 5;
    int lane = threadIdx.x & 31;
    if (gw >= T_TOK) return;
    const float* xr = x + (size_t)gw * HD;
    float acc[NE];
#pragma unroll
    for (int e = 0; e < NE; e++) acc[e] = 0.f;
    float ag = 0.f;
    for (int h = lane; h < HD; h += 32) {
        float xv = xr[h];
        const float4* w = (const float4*)(wr + (size_t)h * NE);
        float4 w0 = w[0], w1 = w[1];
        acc[0] += xv * w0.x; acc[1] += xv * w0.y; acc[2] += xv * w0.z; acc[3] += xv * w0.w;
        acc[4] += xv * w1.x; acc[5] += xv * w1.y; acc[6] += xv * w1.z; acc[7] += xv * w1.w;
        ag += xv * wsg[h];
    }
#pragma unroll
    for (int o = 16; o > 0; o >>= 1) {
#pragma unroll
        for (int e = 0; e < NE; e++) acc[e] += __shfl_xor_sync(0xffffffffu, acc[e], o);
        ag += __shfl_xor_sync(0xffffffffu, ag, o);
    }
    if (lane == 0) {
        int i0 = 0; float v0 = acc[0];
#pragma unroll
        for (int e = 1; e < NE; e++) if (acc[e] > v0) { v0 = acc[e]; i0 = e; }
        int i1 = -1; float v1 = -1e30f;
#pragma unroll
        for (int e = 0; e < NE; e++) if (e != i0 && acc[e] > v1) { v1 = acc[e]; i1 = e; }
        float t  = __expf(v1 - v0);
        g_top_e[gw * 2]     = i0;
        g_top_e[gw * 2 + 1] = i1;
        g_top_p[gw * 2]     = 1.f / (1.f + t);
        g_top_p[gw * 2 + 1] = t / (1.f + t);
        atomicAdd(&g_cnt[i0], 1);
        atomicAdd(&g_cnt[i1], 1);
        g_gate[gw] = 1.f / (1.f + __expf(-ag));
    }
}

// builds tile map, then re-zeroes g_cnt/g_fill for the NEXT call (globals start zeroed)
__global__ void scan_kernel() {
    if (threadIdx.x == 0 && blockIdx.x == 0) {
        int off = 0, nt = 0;
        for (int e = 0; e < NE; e++) {
            g_off[e] = off;
            int c = g_cnt[e];
            for (int r = 0; r < c; r += 128) {
                g_tile_e[nt]    = e;
                g_tile_row0[nt] = off + r;
                g_tile_rows[nt] = (c - r < 128) ? (c - r) : 128;
                nt++;
            }
            off = (off + c + 127) & ~127;
        }
        g_ntiles = nt;
        for (int e = 0; e < NE; e++) { g_cnt[e] = 0; g_fill[e] = 0; }
    }
}

__global__ void scatter_kernel(const float* __restrict__ x) {
    int a = blockIdx.x;
    int t = a >> 1;
    __shared__ int srow;
    int   e = g_top_e[a];
    float p = g_top_p[a];
    if (threadIdx.x == 0) {
        int pos = atomicAdd(&g_fill[e], 1);
        int row = g_off[e] + pos;
        g_row_token[row] = t;
        srow = row;
    }
    __syncthreads();
    int row = srow;
    const float4* src = (const float4*)(x + (size_t)t * HD);
    __half2*      dst = (__half2*)(g_xin + (size_t)row * HD);
    for (int i = threadIdx.x; i < HD / 4; i += blockDim.x) {
        float4 v = src[i];
        dst[2 * i]     = __floats2half2_rn(v.x * p, v.y * p);
        dst[2 * i + 1] = __floats2half2_rn(v.z * p, v.w * p);
    }
}

// ---------------- prep: pure streaming fp32->fp16 cvt (no transpose) ----------------
#define C_WGU  11534336u   // 8*2048*2816/4
#define C_WD   17301504u   // + 8*1408*2048/4
#define C_WSGU 18743296u   // + 2048*2816/4
#define C_WSD  19464192u   // + 1408*2048/4
#define C_END  23658496u   // + 8192*2048/4
__global__ void prep_kernel(const float4* __restrict__ x,
                            const float4* __restrict__ wgu,
                            const float4* __restrict__ wd,
                            const float4* __restrict__ wsgu,
                            const float4* __restrict__ wsd) {
    unsigned i = blockIdx.x * 256u + threadIdx.x;
    const float4* s;
    __half2* d;
    unsigned o;
    if (i < C_WGU)       { s = wgu;  d = (__half2*)g_wgu_h;  o = i; }
    else if (i < C_WD)   { s = wd;   d = (__half2*)g_wd_h;   o = i - C_WGU; }
    else if (i < C_WSGU) { s = wsgu; d = (__half2*)g_wsgu_h; o = i - C_WD; }
    else if (i < C_WSD)  { s = wsd;  d = (__half2*)g_wsd_h;  o = i - C_WSGU; }
    else                 { s = x;    d = (__half2*)g_xh;     o = i - C_WSD; }
    float4 v = s[o];
    d[2 * o]     = __floats2half2_rn(v.x, v.y);
    d[2 * o + 1] = __floats2half2_rn(v.z, v.w);
}

// ---------------- GEMM1: fp16, BM=128, dual BN=64 (g/u), BK=16, ldmatrix(.trans B) ----------------
// stage: A [0,6144) 48B rows | Bg [6144,8448) 144B rows [k][n] | Bu [8448,10752)
__global__ __launch_bounds__(256, 2) void gemm1_kernel() {
    int bx = blockIdx.y;
    bool sh = (bx >= RT_TILES);
    if (!sh && bx >= g_ntiles) return;
    int row0;
    const __half *A, *Bt;
    __half* Hout;
    if (sh) {
        row0 = (bx - RT_TILES) * 128;
        A = g_xh; Bt = g_wsgu_h; Hout = g_shidden;
    } else {
        row0 = g_tile_row0[bx];
        A = g_xin;
        Bt = g_wgu_h + (size_t)g_tile_e[bx] * HD * TWO_I;
        Hout = g_hidden;
    }
    int n0 = blockIdx.x * 64;

    extern __shared__ __half smem[];
    unsigned sb = (unsigned)__cvta_generic_to_shared(smem);

    int tid = threadIdx.x, lane = tid & 31, warp = tid >> 5;
    int wm = warp >> 1, wn = warp & 1;

    // A loader: 1 cp16/thread, rows [m][k]
    int ar_ = tid >> 1, ac_ = (tid & 1) * 8;
    const __half* a_src = A + (size_t)(row0 + ar_) * HD + ac_;
    unsigned a_dst = sb + ar_ * 48 + ac_ * 2;
    // B loader: [k][n] original layout. tid<128: gate rows, tid>=128: up rows.
    int bk_ = (tid & 127) >> 3, bs_ = tid & 7;
    bool isu = tid >= 128;
    const __half* b_src = Bt + (size_t)bk_ * TWO_I + (isu ? ID : 0) + n0 + bs_ * 8;
    unsigned b_dst = sb + (isu ? 8448 : 6144) + bk_ * 144 + bs_ * 16;

    // fragments
    int m8 = lane >> 3, r8 = lane & 7;
    unsigned a_frag[2], bg_frag[2], bu_frag[2];
#pragma unroll
    for (int mt = 0; mt < 2; mt++)
        a_frag[mt] = sb + ((wm * 32 + mt * 16 + ((m8 & 1) << 3) + r8) * 24 + ((m8 >> 1) << 3)) * 2;
    // B .trans: lanes 0-7 -> k0-7 @ n+0 | 8-15 -> k8-15 @ n+0 | 16-23 -> k0-7 @ n+8 | 24-31 -> k8-15 @ n+8
#pragma unroll
    for (int p = 0; p < 2; p++) {
        unsigned ro = ((m8 & 1) * 8 + r8) * 144 + (wn * 32 + p * 16 + (m8 >> 1) * 8) * 2;
        bg_frag[p] = sb + 6144 + ro;
        bu_frag[p] = sb + 8448 + ro;
    }

    float cg[2][4][4], cu[2][4][4];
#pragma unroll
    for (int i = 0; i < 2; i++)
#pragma unroll
        for (int j = 0; j < 4; j++)
#pragma unroll
            for (int q = 0; q < 4; q++) { cg[i][j][q] = 0.f; cu[i][j][q] = 0.f; }

    const int NIT = HD / 16;
#pragma unroll 1
    for (int s = 0; s < NSTG - 1; s++) {
        unsigned off = s * STG1B;
        cp16s(a_dst + off, a_src + s * 16);
        cp16s(b_dst + off, b_src + (size_t)s * 16 * TWO_I);
        cp_commit();
    }
#pragma unroll 1
    for (int it = 0; it < NIT; it++) {
        cp_wait2();
        __syncthreads();
        int lt = it + NSTG - 1;
        if (lt < NIT) {
            unsigned off = (lt & (NSTG - 1)) * STG1B;
            cp16s(a_dst + off, a_src + lt * 16);
            cp16s(b_dst + off, b_src + (size_t)lt * 16 * TWO_I);
        }
        cp_commit();

        unsigned soff = (it & (NSTG - 1)) * STG1B;
        unsigned a[2][4];
        ldsm4(a[0], a_frag[0] + soff);
        ldsm4(a[1], a_frag[1] + soff);
#pragma unroll
        for (int p = 0; p < 2; p++) {
            unsigned bg[4], bu[4];
            ldsm4t(bg, bg_frag[p] + soff);
            ldsm4t(bu, bu_frag[p] + soff);
#pragma unroll
            for (int j = 0; j < 2; j++) {
                int nt = 2 * p + j;
#pragma unroll
                for (int mt = 0; mt < 2; mt++) {
                    mma_f16(cg[mt][nt], a[mt], bg[2 * j], bg[2 * j + 1]);
                    mma_f16(cu[mt][nt], a[mt], bu[2 * j], bu[2 * j + 1]);
                }
            }
        }
    }

#pragma unroll
    for (int mt = 0; mt < 2; mt++) {
#pragma unroll
        for (int nt = 0; nt < 4; nt++) {
            int rb = row0 + wm * 32 + mt * 16 + (lane >> 2);
            int nb = n0 + wn * 32 + nt * 8 + (lane & 3) * 2;
#pragma unroll
            for (int q = 0; q < 4; q++) {
                int rr = rb + ((q >= 2) ? 8 : 0);
                int nn = nb + (q & 1);
                float g = cg[mt][nt][q], u = cu[mt][nt][q];
                float s = 1.f / (1.f + __expf(-g));
                Hout[(size_t)rr * ID + nn] = __float2half_rn(g * s * u);
            }
        }
    }
}

// ---------------- GEMM2: fp16, BM=128, BN=128, BK=16, ldmatrix(.trans B) ----------------
// stage: A [0,6144) 48B rows | B [6144,10496) 272B rows [k][n]
template <bool SH>
__global__ __launch_bounds__(256, 2) void gemm2_kernel(float* __restrict__ out) {
    int bx = blockIdx.y;
    int row0, vrows;
    const __half *A, *Bt;
    if (SH) {
        row0 = bx * 128; vrows = 128;
        A = g_shidden; Bt = g_wsd_h;
    } else {
        if (bx >= g_ntiles) return;
        row0 = g_tile_row0[bx];
        vrows = g_tile_rows[bx];
        A = g_hidden;
        Bt = g_wd_h + (size_t)g_tile_e[bx] * ID * HD;
    }
    int col0 = blockIdx.x * 128;

    extern __shared__ __half smem[];
    unsigned sb = (unsigned)__cvta_generic_to_shared(smem);

    int tid = threadIdx.x, lane = tid & 31, warp = tid >> 5;
    int wm = warp >> 1, wn = warp & 1;

    int ar_ = tid >> 1, ac_ = (tid & 1) * 8;
    const __half* a_src = A + (size_t)(row0 + ar_) * ID + ac_;
    unsigned a_dst = sb + ar_ * 48 + ac_ * 2;
    int bk_ = tid >> 4, bs_ = tid & 15;
    const __half* b_src = Bt + (size_t)bk_ * HD + col0 + bs_ * 8;
    unsigned b_dst = sb + 6144 + bk_ * 272 + bs_ * 16;

    int m8 = lane >> 3, r8 = lane & 7;
    unsigned a_frag[2], b_frag[4];
#pragma unroll
    for (int mt = 0; mt < 2; mt++)
        a_frag[mt] = sb + ((wm * 32 + mt * 16 + ((m8 & 1) << 3) + r8) * 24 + ((m8 >> 1) << 3)) * 2;
#pragma unroll
    for (int p = 0; p < 4; p++)
        b_frag[p] = sb + 6144 + ((m8 & 1) * 8 + r8) * 272 +
                    (wn * 64 + p * 16 + (m8 >> 1) * 8) * 2;

    float c[2][8][4];
#pragma unroll
    for (int i = 0; i < 2; i++)
#pragma unroll
        for (int j = 0; j < 8; j++)
#pragma unroll
            for (int q = 0; q < 4; q++) c[i][j][q] = 0.f;

    const int NIT = ID / 16;
#pragma unroll 1
    for (int s = 0; s < NSTG - 1; s++) {
        unsigned off = s * STG2B;
        cp16s(a_dst + off, a_src + s * 16);
        cp16s(b_dst + off, b_src + (size_t)s * 16 * HD);
        cp_commit();
    }
#pragma unroll 1
    for (int it = 0; it < NIT; it++) {
        cp_wait2();
        __syncthreads();
        int lt = it + NSTG - 1;
        if (lt < NIT) {
            unsigned off = (lt & (NSTG - 1)) * STG2B;
            cp16s(a_dst + off, a_src + lt * 16);
            cp16s(b_dst + off, b_src + (size_t)lt * 16 * HD);
        }
        cp_commit();

        unsigned soff = (it & (NSTG - 1)) * STG2B;
        unsigned a[2][4];
        ldsm4(a[0], a_frag[0] + soff);
        ldsm4(a[1], a_frag[1] + soff);
#pragma unroll
        for (int p = 0; p < 4; p++) {
            unsigned b[4];
            ldsm4t(b, b_frag[p] + soff);
#pragma unroll
            for (int j = 0; j < 2; j++) {
#pragma unroll
                for (int mt = 0; mt < 2; mt++)
                    mma_f16(c[mt][2 * p + j], a[mt], b[2 * j], b[2 * j + 1]);
            }
        }
    }

#pragma unroll
    for (int mt = 0; mt < 2; mt++) {
#pragma unroll
        for (int nt = 0; nt < 8; nt++) {
            int lr0 = wm * 32 + mt * 16 + (lane >> 2);
            int nb  = col0 + wn * 64 + nt * 8 + (lane & 3) * 2;
#pragma unroll
            for (int q = 0; q < 4; q++) {
                int lr = lr0 + ((q >= 2) ? 8 : 0);
                int nn = nb + (q & 1);
                float v = c[mt][nt][q];
                if (SH) {
                    int t = row0 + lr;
                    out[(size_t)t * HD + nn] = g_gate[t] * v;
                } else if (lr < vrows) {
                    int t = g_row_token[row0 + lr];
                    atomicAdd(&out[(size_t)t * HD + nn], v);
                }
            }
        }
    }
}

// ---------------- launch ----------------
extern "C" void kernel_launch(void* const* d_in, const int* in_sizes, int n_in,
                              void* d_out, int out_size) {
    const float* x    = (const float*)d_in[0];
    const float* wr   = (const float*)d_in[1];
    const float* wgu  = (const float*)d_in[2];
    const float* wd   = (const float*)d_in[3];
    const float* wsgu = (const float*)d_in[4];
    const float* wsd  = (const float*)d_in[5];
    const float* wsg  = (const float*)d_in[6];
    float* out = (float*)d_out;

    static int attr_done = 0;
    if (!attr_done) {
        cudaFuncSetAttribute(gemm1_kernel, cudaFuncAttributeMaxDynamicSharedMemorySize, SMEM_G1);
        cudaFuncSetAttribute(gemm2_kernel<true>,  cudaFuncAttributeMaxDynamicSharedMemorySize, SMEM_G2);
        cudaFuncSetAttribute(gemm2_kernel<false>, cudaFuncAttributeMaxDynamicSharedMemorySize, SMEM_G2);
        attr_done = 1;
    }

    router_kernel<<<T_TOK / 8, 256>>>(x, wr, wsg);                 // 0
    scan_kernel<<<1, 1>>>();                                       // 1 (also re-zeroes counters)
    scatter_kernel<<<NA, 256>>>(x);                                // 2
    prep_kernel<<<C_END / 256, 256>>>((const float4*)x, (const float4*)wgu,
                                      (const float4*)wd, (const float4*)wsgu,
                                      (const float4*)wsd);         // 3
    gemm1_kernel<<<dim3(ID / 64, RT_TILES + T_TOK / 128), 256, SMEM_G1>>>();   // 4
    gemm2_kernel<true><<<dim3(HD / 128, T_TOK / 128), 256, SMEM_G2>>>(out);    // 5
    gemm2_kernel<false><<<dim3(HD / 128, RT_TILES), 256, SMEM_G2>>>(out);      // 6
}